// round 2
// baseline (speedup 1.0000x reference)
#include <cuda_runtime.h>
#include <cuda_bf16.h>
#include <math.h>

// Problem constants
#define B_   1024
#define S_   128
#define D_   256
#define H_   2048
#define O_   10
#define V_   10

// Ping-pong hidden-state buffers + token->xh lookup table (scratch: __device__ globals)
__device__ float g_h0[B_ * H_];
__device__ float g_h1[B_ * H_];
__device__ float g_T[V_ * H_];   // T[v,h] = (W_hx @ embed[v])[h] + b_hx[h]

// ---------------------------------------------------------------------------
// Kernel 1: precompute T[v,h]. 10x2048 dots of length 256. Trivial.
// grid (8, 10) x 256 threads
// ---------------------------------------------------------------------------
__global__ void precompute_T_kernel(const float* __restrict__ embed,
                                    const float* __restrict__ W_hx,
                                    const float* __restrict__ b_hx) {
    int h = blockIdx.x * blockDim.x + threadIdx.x;   // 0..2047
    int v = blockIdx.y;                              // 0..9
    if (h >= H_) return;
    const float4* wr = reinterpret_cast<const float4*>(W_hx + (size_t)h * D_);
    const float4* er = reinterpret_cast<const float4*>(embed + (size_t)v * D_);
    float s = 0.f;
#pragma unroll 8
    for (int i = 0; i < D_ / 4; i++) {
        float4 w = wr[i];
        float4 e = er[i];
        s += w.x * e.x + w.y * e.y + w.z * e.z + w.w * e.w;
    }
    g_T[v * H_ + h] = s + b_hx[h];
}

// ---------------------------------------------------------------------------
// Kernel 2: h0[b,h] = tanh(T[x[b,0], h])   (step 0: hx term only, per reference)
// ---------------------------------------------------------------------------
__global__ void init_h_kernel(const int* __restrict__ x) {
    int idx = blockIdx.x * blockDim.x + threadIdx.x;  // b*H + h
    int b = idx >> 11;
    int h = idx & (H_ - 1);
    int tok = x[b * S_];            // x[b][0]
    g_h0[idx] = tanhf(g_T[tok * H_ + h]);
}

// ---------------------------------------------------------------------------
// Kernel 3: one recurrence step, fused GEMM + bias + xh-lookup + tanh.
//   C[b,h] = tanh( sum_k A[b,k]*W_hh[h,k] + T[x[b,t],h] + b_hh[h] )
// Classic 128x128x8 register-blocked SGEMM, 256 threads, 8x8 per thread.
// grid (H/128=16, B/128=8) = 128 CTAs -> one wave.
// ---------------------------------------------------------------------------
#define BM 128
#define BN 128
#define BK 8
#define TM 8
#define TN 8

__global__ __launch_bounds__(256, 1)
void rnn_step_kernel(int parity,
                     const float* __restrict__ W,      // W_hh [H,H] row-major (h,k)
                     const float* __restrict__ b_hh,
                     const int*   __restrict__ x,
                     int t) {
    const float* __restrict__ A = parity ? g_h1 : g_h0;
    float*       __restrict__ C = parity ? g_h0 : g_h1;

    __shared__ float As[BK][BM];
    __shared__ float Bs[BK][BN];

    const int tid = threadIdx.x;
    const int bm0 = blockIdx.y * BM;     // batch-tile origin
    const int bn0 = blockIdx.x * BN;     // hidden-tile origin

    // Loaders: each thread loads one float4 of A-tile and one of B-tile per k-step
    const int lrow = tid >> 1;           // 0..127
    const int lseg = tid & 1;            // 0..1 (which float4 of the 8-wide row)
    const float* Aptr = A + (size_t)(bm0 + lrow) * H_ + lseg * 4;
    const float* Wptr = W + (size_t)(bn0 + lrow) * H_ + lseg * 4;

    // Compute mapping: 16x16 thread grid, each thread owns an 8x8 micro-tile
    const int ty = tid >> 4;             // 0..15 -> rows
    const int tx = tid & 15;             // 0..15 -> cols

    float acc[TM][TN];
#pragma unroll
    for (int i = 0; i < TM; i++)
#pragma unroll
        for (int j = 0; j < TN; j++) acc[i][j] = 0.f;

    for (int k0 = 0; k0 < H_; k0 += BK) {
        float4 a4 = *reinterpret_cast<const float4*>(Aptr + k0);
        float4 b4 = *reinterpret_cast<const float4*>(Wptr + k0);
        As[lseg * 4 + 0][lrow] = a4.x;
        As[lseg * 4 + 1][lrow] = a4.y;
        As[lseg * 4 + 2][lrow] = a4.z;
        As[lseg * 4 + 3][lrow] = a4.w;
        Bs[lseg * 4 + 0][lrow] = b4.x;
        Bs[lseg * 4 + 1][lrow] = b4.y;
        Bs[lseg * 4 + 2][lrow] = b4.z;
        Bs[lseg * 4 + 3][lrow] = b4.w;
        __syncthreads();

#pragma unroll
        for (int k = 0; k < BK; k++) {
            float af[TM], bf[TN];
#pragma unroll
            for (int i = 0; i < TM; i++) af[i] = As[k][ty * TM + i];
#pragma unroll
            for (int j = 0; j < TN; j++) bf[j] = Bs[k][tx * TN + j];
#pragma unroll
            for (int i = 0; i < TM; i++)
#pragma unroll
                for (int j = 0; j < TN; j++) acc[i][j] += af[i] * bf[j];
        }
        __syncthreads();
    }

    // Fused epilogue: + T[x[b,t],h] + b_hh[h], tanh, store
#pragma unroll
    for (int i = 0; i < TM; i++) {
        int b = bm0 + ty * TM + i;
        int tok = x[b * S_ + t];
        const float* Trow = g_T + tok * H_;
#pragma unroll
        for (int jj = 0; jj < TN; jj += 4) {
            int h = bn0 + tx * TN + jj;
            float4 o;
            o.x = tanhf(acc[i][jj + 0] + Trow[h + 0] + b_hh[h + 0]);
            o.y = tanhf(acc[i][jj + 1] + Trow[h + 1] + b_hh[h + 1]);
            o.z = tanhf(acc[i][jj + 2] + Trow[h + 2] + b_hh[h + 2]);
            o.w = tanhf(acc[i][jj + 3] + Trow[h + 3] + b_hh[h + 3]);
            *reinterpret_cast<float4*>(C + (size_t)b * H_ + h) = o;
        }
    }
}

// ---------------------------------------------------------------------------
// Kernel 4: o = hT @ W_oh^T + b_oh ; softmax over O=10. One CTA per batch row.
// Final hidden state lives in g_h1 (127 steps from g_h0).
// ---------------------------------------------------------------------------
__global__ __launch_bounds__(256)
void output_softmax_kernel(const float* __restrict__ W_oh,
                           const float* __restrict__ b_oh,
                           float* __restrict__ out) {
    const int b = blockIdx.x;
    const int tid = threadIdx.x;
    const float* hrow = g_h1 + (size_t)b * H_;

    float acc[O_];
#pragma unroll
    for (int j = 0; j < O_; j++) acc[j] = 0.f;

    for (int k = tid; k < H_; k += 256) {
        float hv = hrow[k];
#pragma unroll
        for (int j = 0; j < O_; j++) acc[j] += hv * W_oh[j * H_ + k];
    }

    // warp reduce
#pragma unroll
    for (int off = 16; off > 0; off >>= 1)
#pragma unroll
        for (int j = 0; j < O_; j++)
            acc[j] += __shfl_down_sync(0xffffffffu, acc[j], off);

    __shared__ float part[8][O_];
    if ((tid & 31) == 0) {
#pragma unroll
        for (int j = 0; j < O_; j++) part[tid >> 5][j] = acc[j];
    }
    __syncthreads();

    if (tid == 0) {
        float o[O_];
#pragma unroll
        for (int j = 0; j < O_; j++) {
            float s = b_oh[j];
#pragma unroll
            for (int w = 0; w < 8; w++) s += part[w][j];
            o[j] = s;
        }
        float m = o[0];
#pragma unroll
        for (int j = 1; j < O_; j++) m = fmaxf(m, o[j]);
        float s = 0.f;
#pragma unroll
        for (int j = 0; j < O_; j++) { o[j] = expf(o[j] - m); s += o[j]; }
        float inv = 1.f / s;
#pragma unroll
        for (int j = 0; j < O_; j++) out[b * O_ + j] = o[j] * inv;
    }
}

// ---------------------------------------------------------------------------
// Launch: all graph-capturable, no allocs, no syncs.
// Inputs (metadata order): x, embed, W_hx, b_hx, W_hh, b_hh, W_oh, b_oh
// ---------------------------------------------------------------------------
extern "C" void kernel_launch(void* const* d_in, const int* in_sizes, int n_in,
                              void* d_out, int out_size) {
    const int*   x     = (const int*)  d_in[0];
    const float* embed = (const float*)d_in[1];
    const float* W_hx  = (const float*)d_in[2];
    const float* b_hx  = (const float*)d_in[3];
    const float* W_hh  = (const float*)d_in[4];
    const float* b_hh  = (const float*)d_in[5];
    const float* W_oh  = (const float*)d_in[6];
    const float* b_oh  = (const float*)d_in[7];
    float* out = (float*)d_out;

    // 1) token -> xh lookup table (kills the 137-GFLOP embed GEMM)
    precompute_T_kernel<<<dim3(H_ / 256, V_), 256>>>(embed, W_hx, b_hx);

    // 2) h0 = tanh(T[x[:,0]])
    init_h_kernel<<<(B_ * H_) / 256, 256>>>(x);

    // 3) 127 fused recurrence steps (ping-pong g_h0 <-> g_h1)
    dim3 grid(H_ / BN, B_ / BM);   // (16, 8)
    for (int t = 1; t < S_; t++) {
        int parity = (t - 1) & 1;  // t=1 reads g_h0 writes g_h1; final (t=127) writes g_h1
        rnn_step_kernel<<<grid, 256>>>(parity, W_hh, b_hh, x, t);
    }

    // 4) output projection + softmax (reads g_h1)
    output_softmax_kernel<<<B_, 256>>>(W_oh, b_oh, out);
}

// round 3
// speedup vs baseline: 1.0019x; 1.0019x over previous
#include <cuda_runtime.h>
#include <cuda_bf16.h>
#include <math.h>

// Problem constants
#define B_   1024
#define S_   128
#define D_   256
#define H_   2048
#define O_   10
#define V_   10

// Ping-pong hidden-state buffers + token->xh lookup table (scratch: __device__ globals)
__device__ float g_h0[B_ * H_];
__device__ float g_h1[B_ * H_];
__device__ float g_T[V_ * H_];   // T[v,h] = (W_hx @ embed[v])[h] + b_hx[h]

// ---------------------------------------------------------------------------
// Kernel 1: precompute T[v,h]. 10x2048 dots of length 256. Trivial.
// grid (8, 10) x 256 threads
// ---------------------------------------------------------------------------
__global__ void precompute_T_kernel(const float* __restrict__ embed,
                                    const float* __restrict__ W_hx,
                                    const float* __restrict__ b_hx) {
    int h = blockIdx.x * blockDim.x + threadIdx.x;   // 0..2047
    int v = blockIdx.y;                              // 0..9
    if (h >= H_) return;
    const float4* wr = reinterpret_cast<const float4*>(W_hx + (size_t)h * D_);
    const float4* er = reinterpret_cast<const float4*>(embed + (size_t)v * D_);
    float s = 0.f;
#pragma unroll 8
    for (int i = 0; i < D_ / 4; i++) {
        float4 w = wr[i];
        float4 e = er[i];
        s += w.x * e.x + w.y * e.y + w.z * e.z + w.w * e.w;
    }
    g_T[v * H_ + h] = s + b_hx[h];
}

// ---------------------------------------------------------------------------
// Kernel 2: h0[b,h] = tanh(T[x[b,0], h])   (step 0: hx term only, per reference)
// ---------------------------------------------------------------------------
__global__ void init_h_kernel(const int* __restrict__ x) {
    int idx = blockIdx.x * blockDim.x + threadIdx.x;  // b*H + h
    int b = idx >> 11;
    int h = idx & (H_ - 1);
    int tok = x[b * S_];            // x[b][0]
    g_h0[idx] = tanhf(g_T[tok * H_ + h]);
}

// ---------------------------------------------------------------------------
// Kernel 3: one recurrence step, fused GEMM + bias + xh-lookup + tanh.
//   C[b,h] = tanh( sum_k A[b,k]*W_hh[h,k] + T[x[b,t],h] + b_hh[h] )
// Classic 128x128x8 register-blocked SGEMM, 256 threads, 8x8 per thread.
// grid (H/128=16, B/128=8) = 128 CTAs -> one wave.
// ---------------------------------------------------------------------------
#define BM 128
#define BN 128
#define BK 8
#define TM 8
#define TN 8

__global__ __launch_bounds__(256, 1)
void rnn_step_kernel(int parity,
                     const float* __restrict__ W,      // W_hh [H,H] row-major (h,k)
                     const float* __restrict__ b_hh,
                     const int*   __restrict__ x,
                     int t) {
    const float* __restrict__ A = parity ? g_h1 : g_h0;
    float*       __restrict__ C = parity ? g_h0 : g_h1;

    __shared__ float As[BK][BM];
    __shared__ float Bs[BK][BN];

    const int tid = threadIdx.x;
    const int bm0 = blockIdx.y * BM;     // batch-tile origin
    const int bn0 = blockIdx.x * BN;     // hidden-tile origin

    // Loaders: each thread loads one float4 of A-tile and one of B-tile per k-step
    const int lrow = tid >> 1;           // 0..127
    const int lseg = tid & 1;            // 0..1 (which float4 of the 8-wide row)
    const float* Aptr = A + (size_t)(bm0 + lrow) * H_ + lseg * 4;
    const float* Wptr = W + (size_t)(bn0 + lrow) * H_ + lseg * 4;

    // Compute mapping: 16x16 thread grid, each thread owns an 8x8 micro-tile
    const int ty = tid >> 4;             // 0..15 -> rows
    const int tx = tid & 15;             // 0..15 -> cols

    float acc[TM][TN];
#pragma unroll
    for (int i = 0; i < TM; i++)
#pragma unroll
        for (int j = 0; j < TN; j++) acc[i][j] = 0.f;

    for (int k0 = 0; k0 < H_; k0 += BK) {
        float4 a4 = *reinterpret_cast<const float4*>(Aptr + k0);
        float4 b4 = *reinterpret_cast<const float4*>(Wptr + k0);
        As[lseg * 4 + 0][lrow] = a4.x;
        As[lseg * 4 + 1][lrow] = a4.y;
        As[lseg * 4 + 2][lrow] = a4.z;
        As[lseg * 4 + 3][lrow] = a4.w;
        Bs[lseg * 4 + 0][lrow] = b4.x;
        Bs[lseg * 4 + 1][lrow] = b4.y;
        Bs[lseg * 4 + 2][lrow] = b4.z;
        Bs[lseg * 4 + 3][lrow] = b4.w;
        __syncthreads();

#pragma unroll
        for (int k = 0; k < BK; k++) {
            float af[TM], bf[TN];
#pragma unroll
            for (int i = 0; i < TM; i++) af[i] = As[k][ty * TM + i];
#pragma unroll
            for (int j = 0; j < TN; j++) bf[j] = Bs[k][tx * TN + j];
#pragma unroll
            for (int i = 0; i < TM; i++)
#pragma unroll
                for (int j = 0; j < TN; j++) acc[i][j] += af[i] * bf[j];
        }
        __syncthreads();
    }

    // Fused epilogue: + T[x[b,t],h] + b_hh[h], tanh, store
#pragma unroll
    for (int i = 0; i < TM; i++) {
        int b = bm0 + ty * TM + i;
        int tok = x[b * S_ + t];
        const float* Trow = g_T + tok * H_;
#pragma unroll
        for (int jj = 0; jj < TN; jj += 4) {
            int h = bn0 + tx * TN + jj;
            float4 o;
            o.x = tanhf(acc[i][jj + 0] + Trow[h + 0] + b_hh[h + 0]);
            o.y = tanhf(acc[i][jj + 1] + Trow[h + 1] + b_hh[h + 1]);
            o.z = tanhf(acc[i][jj + 2] + Trow[h + 2] + b_hh[h + 2]);
            o.w = tanhf(acc[i][jj + 3] + Trow[h + 3] + b_hh[h + 3]);
            *reinterpret_cast<float4*>(C + (size_t)b * H_ + h) = o;
        }
    }
}

// ---------------------------------------------------------------------------
// Kernel 4: o = hT @ W_oh^T + b_oh ; softmax over O=10. One CTA per batch row.
// Final hidden state lives in g_h1 (127 steps from g_h0).
// ---------------------------------------------------------------------------
__global__ __launch_bounds__(256)
void output_softmax_kernel(const float* __restrict__ W_oh,
                           const float* __restrict__ b_oh,
                           float* __restrict__ out) {
    const int b = blockIdx.x;
    const int tid = threadIdx.x;
    const float* hrow = g_h1 + (size_t)b * H_;

    float acc[O_];
#pragma unroll
    for (int j = 0; j < O_; j++) acc[j] = 0.f;

    for (int k = tid; k < H_; k += 256) {
        float hv = hrow[k];
#pragma unroll
        for (int j = 0; j < O_; j++) acc[j] += hv * W_oh[j * H_ + k];
    }

    // warp reduce
#pragma unroll
    for (int off = 16; off > 0; off >>= 1)
#pragma unroll
        for (int j = 0; j < O_; j++)
            acc[j] += __shfl_down_sync(0xffffffffu, acc[j], off);

    __shared__ float part[8][O_];
    if ((tid & 31) == 0) {
#pragma unroll
        for (int j = 0; j < O_; j++) part[tid >> 5][j] = acc[j];
    }
    __syncthreads();

    if (tid == 0) {
        float o[O_];
#pragma unroll
        for (int j = 0; j < O_; j++) {
            float s = b_oh[j];
#pragma unroll
            for (int w = 0; w < 8; w++) s += part[w][j];
            o[j] = s;
        }
        float m = o[0];
#pragma unroll
        for (int j = 1; j < O_; j++) m = fmaxf(m, o[j]);
        float s = 0.f;
#pragma unroll
        for (int j = 0; j < O_; j++) { o[j] = expf(o[j] - m); s += o[j]; }
        float inv = 1.f / s;
#pragma unroll
        for (int j = 0; j < O_; j++) out[b * O_ + j] = o[j] * inv;
    }
}

// ---------------------------------------------------------------------------
// Launch: all graph-capturable, no allocs, no syncs.
// Inputs (metadata order): x, embed, W_hx, b_hx, W_hh, b_hh, W_oh, b_oh
// ---------------------------------------------------------------------------
extern "C" void kernel_launch(void* const* d_in, const int* in_sizes, int n_in,
                              void* d_out, int out_size) {
    const int*   x     = (const int*)  d_in[0];
    const float* embed = (const float*)d_in[1];
    const float* W_hx  = (const float*)d_in[2];
    const float* b_hx  = (const float*)d_in[3];
    const float* W_hh  = (const float*)d_in[4];
    const float* b_hh  = (const float*)d_in[5];
    const float* W_oh  = (const float*)d_in[6];
    const float* b_oh  = (const float*)d_in[7];
    float* out = (float*)d_out;

    // 1) token -> xh lookup table (kills the 137-GFLOP embed GEMM)
    precompute_T_kernel<<<dim3(H_ / 256, V_), 256>>>(embed, W_hx, b_hx);

    // 2) h0 = tanh(T[x[:,0]])
    init_h_kernel<<<(B_ * H_) / 256, 256>>>(x);

    // 3) 127 fused recurrence steps (ping-pong g_h0 <-> g_h1)
    dim3 grid(H_ / BN, B_ / BM);   // (16, 8)
    for (int t = 1; t < S_; t++) {
        int parity = (t - 1) & 1;  // t=1 reads g_h0 writes g_h1; final (t=127) writes g_h1
        rnn_step_kernel<<<grid, 256>>>(parity, W_hh, b_hh, x, t);
    }

    // 4) output projection + softmax (reads g_h1)
    output_softmax_kernel<<<B_, 256>>>(W_oh, b_oh, out);
}

// round 4
// speedup vs baseline: 3.5703x; 3.5635x over previous
#include <cuda_runtime.h>
#include <cuda_bf16.h>
#include <math.h>
#include <stdint.h>

// Problem constants
#define B_   1024
#define S_   128
#define D_   256
#define H_   2048
#define O_   10
#define V_   10

// Scratch (__device__ globals — no allocs allowed)
__device__ float g_h0[B_ * H_];
__device__ float g_h1[B_ * H_];
__device__ float g_T[V_ * H_];      // T[v,h] = (W_hx @ embed[v])[h] + b_hx[h]
__device__ float g_Wt[H_ * H_];     // tf32-rounded copy of W_hh

// round-to-nearest tf32 (result kept in fp32 bit pattern, low mantissa zeroed)
__device__ __forceinline__ float tf32r(float x) {
    uint32_t u;
    asm("cvt.rna.tf32.f32 %0, %1;" : "=r"(u) : "f"(x));
    return __uint_as_float(u);
}

// ---------------------------------------------------------------------------
// Kernel 1: T[v,h] = dot(W_hx[h,:], embed[v,:]) + b_hx[h]
// ---------------------------------------------------------------------------
__global__ void precompute_T_kernel(const float* __restrict__ embed,
                                    const float* __restrict__ W_hx,
                                    const float* __restrict__ b_hx) {
    int h = blockIdx.x * blockDim.x + threadIdx.x;
    int v = blockIdx.y;
    if (h >= H_) return;
    const float4* wr = reinterpret_cast<const float4*>(W_hx + (size_t)h * D_);
    const float4* er = reinterpret_cast<const float4*>(embed + (size_t)v * D_);
    float s = 0.f;
#pragma unroll 8
    for (int i = 0; i < D_ / 4; i++) {
        float4 w = wr[i];
        float4 e = er[i];
        s += w.x * e.x + w.y * e.y + w.z * e.z + w.w * e.w;
    }
    g_T[v * H_ + h] = s + b_hx[h];
}

// ---------------------------------------------------------------------------
// Kernel 1b: tf32-round W_hh into g_Wt
// ---------------------------------------------------------------------------
__global__ void round_W_kernel(const float* __restrict__ W) {
    int i = blockIdx.x * blockDim.x + threadIdx.x;
    g_Wt[i] = tf32r(W[i]);
}

// ---------------------------------------------------------------------------
// Kernel 2: h0 = tanh(T[x[:,0]]), rounded to tf32 for the first MMA
// ---------------------------------------------------------------------------
__global__ void init_h_kernel(const int* __restrict__ x) {
    int idx = blockIdx.x * blockDim.x + threadIdx.x;
    int b = idx >> 11;
    int h = idx & (H_ - 1);
    int tok = x[b * S_];
    g_h0[idx] = tf32r(tanhf(g_T[tok * H_ + h]));
}

// ---------------------------------------------------------------------------
// Kernel 3: recurrence step on tensor cores (tf32 mma.sync m16n8k8).
//   C = tf32round( tanh( A @ Wt^T + T[x[:,t]] + b_hh ) )
// Tile: BM=128 x BN=128 x BK=16, 256 threads, warp grid 2x4, warp tile 64x32.
//
// Smem layout (per 256-row buffer, 16 floats/row, no pad):
//   row r (A rows 0..127, B rows 128..255) stores k-values permuted:
//     p(k) = (k&3)*4 + (k>>2), quad-swizzled: quad' = quad ^ ((r>>1)&3)
//   => thread (g=lane>>2, c=lane&3) fragment = ONE float4 at [r][4*(c^swz)]
//      covering k = {c, c+4, c+8, c+12} (both k-steps of the 16-k tile).
//   Stores (STS.32) and fragment loads (LDS.128) are bank-conflict-free.
// ---------------------------------------------------------------------------
#define BM 128
#define BN 128
#define BK 16
#define NIT (H_ / BK)   // 128

__device__ __forceinline__ void mma_tf32(float* d,
                                         float a0, float a1, float a2, float a3,
                                         float b0, float b1) {
    uint32_t A0 = __float_as_uint(a0), A1 = __float_as_uint(a1);
    uint32_t A2 = __float_as_uint(a2), A3 = __float_as_uint(a3);
    uint32_t B0 = __float_as_uint(b0), B1 = __float_as_uint(b1);
    asm volatile(
        "mma.sync.aligned.m16n8k8.row.col.f32.tf32.tf32.f32 "
        "{%0,%1,%2,%3}, {%4,%5,%6,%7}, {%8,%9}, {%0,%1,%2,%3};\n"
        : "+f"(d[0]), "+f"(d[1]), "+f"(d[2]), "+f"(d[3])
        : "r"(A0), "r"(A1), "r"(A2), "r"(A3), "r"(B0), "r"(B1));
}

__global__ __launch_bounds__(256, 1)
void rnn_step_tc(int parity,
                 const float* __restrict__ bhh,
                 const int*   __restrict__ x,
                 int t) {
    const float* __restrict__ A = parity ? g_h1 : g_h0;
    float*       __restrict__ C = parity ? g_h0 : g_h1;
    const float* __restrict__ W = g_Wt;

    __shared__ float smem[2][256 * 16];

    const int tid = threadIdx.x;
    const int bm0 = blockIdx.y * BM;
    const int bn0 = blockIdx.x * BN;

    // ---- loader mapping: 4 threads per row, 1 float4 (quad) each ----
    const int lq = tid & 3;          // which k-quad (global k offset lq*4)
    const int lr = tid >> 2;         // 0..63
    const float* gA0 = A + (size_t)(bm0 + lr)      * H_ + lq * 4;
    const float* gA1 = A + (size_t)(bm0 + lr + 64) * H_ + lq * 4;
    const float* gW0 = W + (size_t)(bn0 + lr)      * H_ + lq * 4;
    const float* gW1 = W + (size_t)(bn0 + lr + 64) * H_ + lq * 4;
    const int RA0 = lr, RA1 = lr + 64, RB0 = 128 + lr, RB1 = 128 + lr + 64;

    // ---- mma fragment mapping ----
    const int warp = tid >> 5, lane = tid & 31;
    const int wm = warp >> 2;        // 0..1
    const int wn = warp & 3;         // 0..3
    const int g  = lane >> 2;        // 0..7
    const int cc = lane & 3;         // 0..3

    int offAlo[4], offB[4];
#pragma unroll
    for (int f = 0; f < 4; f++) {
        int rl = wm * 64 + f * 16 + g;
        offAlo[f] = rl * 16 + 4 * (cc ^ ((rl >> 1) & 3));
    }
#pragma unroll
    for (int n = 0; n < 4; n++) {
        int rb = 128 + wn * 32 + n * 8 + g;
        offB[n] = rb * 16 + 4 * (cc ^ ((rb >> 1) & 3));
    }

    float acc[4][4][4];
#pragma unroll
    for (int f = 0; f < 4; f++)
#pragma unroll
        for (int n = 0; n < 4; n++)
#pragma unroll
            for (int k = 0; k < 4; k++) acc[f][n][k] = 0.f;

    // STS of one loaded quad: element j (global k = lq*4+j? no: k = 4*lq + j,
    // permuted position p = j*4 + lq) -> smem[R*16 + 4*(j ^ ((R>>1)&3)) + lq]
    float4 pf0, pf1, pf2, pf3;

#define STS_ROW(SB, R, V)                                  \
    do {                                                   \
        int _x = ((R) >> 1) & 3;                           \
        int _b = (R) * 16 + lq;                            \
        (SB)[_b + 4 * (0 ^ _x)] = (V).x;                   \
        (SB)[_b + 4 * (1 ^ _x)] = (V).y;                   \
        (SB)[_b + 4 * (2 ^ _x)] = (V).z;                   \
        (SB)[_b + 4 * (3 ^ _x)] = (V).w;                   \
    } while (0)

    // ---- prologue: tile0 -> smem[0]; prefetch tile1 -> regs ----
    pf0 = *(const float4*)(gA0);
    pf1 = *(const float4*)(gA1);
    pf2 = *(const float4*)(gW0);
    pf3 = *(const float4*)(gW1);
    {
        float* sb = smem[0];
        STS_ROW(sb, RA0, pf0); STS_ROW(sb, RA1, pf1);
        STS_ROW(sb, RB0, pf2); STS_ROW(sb, RB1, pf3);
    }
    pf0 = *(const float4*)(gA0 + BK);
    pf1 = *(const float4*)(gA1 + BK);
    pf2 = *(const float4*)(gW0 + BK);
    pf3 = *(const float4*)(gW1 + BK);
    __syncthreads();

    int buf = 0;
#pragma unroll 1
    for (int it = 0; it < NIT; ++it) {
        // stage prefetched tile (it+1) into the other buffer
        if (it + 1 < NIT) {
            float* sb1 = smem[buf ^ 1];
            STS_ROW(sb1, RA0, pf0); STS_ROW(sb1, RA1, pf1);
            STS_ROW(sb1, RB0, pf2); STS_ROW(sb1, RB1, pf3);
        }
        // issue loads for tile (it+2)
        if (it + 2 < NIT) {
            int k0 = (it + 2) * BK;
            pf0 = *(const float4*)(gA0 + k0);
            pf1 = *(const float4*)(gA1 + k0);
            pf2 = *(const float4*)(gW0 + k0);
            pf3 = *(const float4*)(gW1 + k0);
        }

        // compute on current buffer
        const float* sb = smem[buf];
        float4 alo[4], ahi[4], bq[4];
#pragma unroll
        for (int f = 0; f < 4; f++) {
            alo[f] = *(const float4*)(sb + offAlo[f]);
            ahi[f] = *(const float4*)(sb + offAlo[f] + 128);   // row+8, same swizzle
        }
#pragma unroll
        for (int n = 0; n < 4; n++) bq[n] = *(const float4*)(sb + offB[n]);

        // k-step 0: k = {cc, cc+4}
#pragma unroll
        for (int f = 0; f < 4; f++)
#pragma unroll
            for (int n = 0; n < 4; n++)
                mma_tf32(acc[f][n], alo[f].x, ahi[f].x, alo[f].y, ahi[f].y,
                         bq[n].x, bq[n].y);
        // k-step 1: k = {cc+8, cc+12}
#pragma unroll
        for (int f = 0; f < 4; f++)
#pragma unroll
            for (int n = 0; n < 4; n++)
                mma_tf32(acc[f][n], alo[f].z, ahi[f].z, alo[f].w, ahi[f].w,
                         bq[n].z, bq[n].w);

        __syncthreads();
        buf ^= 1;
    }

    // ---- fused epilogue: + T[x[b,t]] + b_hh, tanh, tf32-round, store ----
#pragma unroll
    for (int f = 0; f < 4; f++) {
        int rlo = bm0 + wm * 64 + f * 16 + g;
        int rhi = rlo + 8;
        int tlo = x[rlo * S_ + t];
        int thi = x[rhi * S_ + t];
        const float* Tlo = g_T + tlo * H_;
        const float* Thi = g_T + thi * H_;
#pragma unroll
        for (int n = 0; n < 4; n++) {
            int col = bn0 + wn * 32 + n * 8 + cc * 2;
            float bb0 = bhh[col], bb1 = bhh[col + 1];
            float2 o;
            o.x = tf32r(tanhf(acc[f][n][0] + Tlo[col]     + bb0));
            o.y = tf32r(tanhf(acc[f][n][1] + Tlo[col + 1] + bb1));
            *(float2*)(C + (size_t)rlo * H_ + col) = o;
            o.x = tf32r(tanhf(acc[f][n][2] + Thi[col]     + bb0));
            o.y = tf32r(tanhf(acc[f][n][3] + Thi[col + 1] + bb1));
            *(float2*)(C + (size_t)rhi * H_ + col) = o;
        }
    }
#undef STS_ROW
}

// ---------------------------------------------------------------------------
// Kernel 4: o = hT @ W_oh^T + b_oh ; softmax over O=10.
// ---------------------------------------------------------------------------
__global__ __launch_bounds__(256)
void output_softmax_kernel(const float* __restrict__ W_oh,
                           const float* __restrict__ b_oh,
                           float* __restrict__ out) {
    const int b = blockIdx.x;
    const int tid = threadIdx.x;
    const float* hrow = g_h1 + (size_t)b * H_;

    float acc[O_];
#pragma unroll
    for (int j = 0; j < O_; j++) acc[j] = 0.f;

    for (int k = tid; k < H_; k += 256) {
        float hv = hrow[k];
#pragma unroll
        for (int j = 0; j < O_; j++) acc[j] += hv * W_oh[j * H_ + k];
    }
#pragma unroll
    for (int off = 16; off > 0; off >>= 1)
#pragma unroll
        for (int j = 0; j < O_; j++)
            acc[j] += __shfl_down_sync(0xffffffffu, acc[j], off);

    __shared__ float part[8][O_];
    if ((tid & 31) == 0) {
#pragma unroll
        for (int j = 0; j < O_; j++) part[tid >> 5][j] = acc[j];
    }
    __syncthreads();

    if (tid == 0) {
        float o[O_];
#pragma unroll
        for (int j = 0; j < O_; j++) {
            float s = b_oh[j];
#pragma unroll
            for (int w = 0; w < 8; w++) s += part[w][j];
            o[j] = s;
        }
        float m = o[0];
#pragma unroll
        for (int j = 1; j < O_; j++) m = fmaxf(m, o[j]);
        float s = 0.f;
#pragma unroll
        for (int j = 0; j < O_; j++) { o[j] = expf(o[j] - m); s += o[j]; }
        float inv = 1.f / s;
#pragma unroll
        for (int j = 0; j < O_; j++) out[b * O_ + j] = o[j] * inv;
    }
}

// ---------------------------------------------------------------------------
// Launch (graph-capturable, no allocs/syncs).
// Inputs: x, embed, W_hx, b_hx, W_hh, b_hh, W_oh, b_oh
// ---------------------------------------------------------------------------
extern "C" void kernel_launch(void* const* d_in, const int* in_sizes, int n_in,
                              void* d_out, int out_size) {
    const int*   x     = (const int*)  d_in[0];
    const float* embed = (const float*)d_in[1];
    const float* W_hx  = (const float*)d_in[2];
    const float* b_hx  = (const float*)d_in[3];
    const float* W_hh  = (const float*)d_in[4];
    const float* b_hh  = (const float*)d_in[5];
    const float* W_oh  = (const float*)d_in[6];
    const float* b_oh  = (const float*)d_in[7];
    float* out = (float*)d_out;

    precompute_T_kernel<<<dim3(H_ / 256, V_), 256>>>(embed, W_hx, b_hx);
    round_W_kernel<<<(H_ * H_) / 256, 256>>>(W_hh);
    init_h_kernel<<<(B_ * H_) / 256, 256>>>(x);

    dim3 grid(H_ / BN, B_ / BM);   // (16, 8) = 128 CTAs
    for (int t = 1; t < S_; t++) {
        int parity = (t - 1) & 1;
        rnn_step_tc<<<grid, 256>>>(parity, b_hh, x, t);
    }

    output_softmax_kernel<<<B_, 256>>>(W_oh, b_oh, out);
}